// round 11
// baseline (speedup 1.0000x reference)
#include <cuda_runtime.h>
#include <cstdint>

#define B_  4
#define TQ  512
#define TK  512
#define QD  1024
#define CD  256

// Scratch: projected tensors TRANSPOSED [b][c][row] (C-major). Zeroed each call.
__device__ float g_q2t[B_ * CD * TQ];
__device__ float g_k2t[B_ * CD * TK];

__device__ __forceinline__ uint32_t smem_u32(const void* p) {
    uint32_t a;
    asm("{ .reg .u64 t; cvta.to.shared.u64 t, %1; cvt.u32.u64 %0, t; }"
        : "=r"(a) : "l"(p));
    return a;
}
__device__ __forceinline__ void cp_async16(uint32_t saddr, const void* g) {
    asm volatile("cp.async.cg.shared.global [%0], [%1], 16;" :: "r"(saddr), "l"(g));
}
__device__ __forceinline__ void cp_commit() {
    asm volatile("cp.async.commit_group;" ::: "memory");
}
__device__ __forceinline__ void cp_wait1() {
    asm volatile("cp.async.wait_group 1;" ::: "memory");
}
__device__ __forceinline__ void cp_wait0() {
    asm volatile("cp.async.wait_group 0;" ::: "memory");
}
__device__ __forceinline__ void mma_tf32(float* d, const uint32_t* a, const uint32_t* b) {
    asm volatile(
        "mma.sync.aligned.m16n8k8.row.col.f32.tf32.tf32.f32 "
        "{%0,%1,%2,%3}, {%4,%5,%6,%7}, {%8,%9}, {%0,%1,%2,%3};\n"
        : "+f"(d[0]), "+f"(d[1]), "+f"(d[2]), "+f"(d[3])
        : "r"(a[0]), "r"(a[1]), "r"(a[2]), "r"(a[3]), "r"(b[0]), "r"(b[1]));
}
__device__ __forceinline__ float tanh_fast(float x) {
    float y;
    asm("tanh.approx.f32 %0, %1;" : "=f"(y) : "f"(x));
    return y;
}
// Round fp32 bit pattern so tf32 truncation (drop 13 bits) becomes round-to-nearest.
#define TF32_RN(u) ((u) + 0x1000u)

// ---------------------------------------------------------------------------
// Projection via mma.sync tf32 with K split across 2 CTAs (atomic accumulate).
// C[m][n] = sum_k X[m][k]*W[k][n]; scratch pre-zeroed, each K-half atomicAdds.
// A smem [m][k] stride 68; B smem natural W layout [k][n] stride 72.
// 8 warps = 4(M) x 2(N), warp tile 32x32, BK=64, 2-stage cp.async (occ 2).
// grid (16, 4, 4): x = m-tile, y = n-tile, z = (khalf<<1) | is_key.
// ---------------------------------------------------------------------------
#define BM     128
#define BN     64
#define BK     64
#define KSPL   512                       // K per CTA
#define LDS_A  68
#define LDS_B  72
#define A_FL   (BM * LDS_A)              // 8704 floats
#define B_FL   (BK * LDS_B)              // 4608 floats
#define NITER  (KSPL / BK)               // 8
#define STAGES 2
#define DYN_SMEM (STAGES * (A_FL + B_FL) * 4)   // 106496 B -> 2 CTAs/SM

__global__ __launch_bounds__(256) void proj_mma_kernel(
    const float* __restrict__ Xq, const float* __restrict__ Xk,
    const float* __restrict__ Wq, const float* __restrict__ Wk)
{
    extern __shared__ float sm[];
    const uint32_t smb = smem_u32(sm);

    float*   Abuf[STAGES];
    float*   Bbuf[STAGES];
    uint32_t a_u[STAGES], b_u[STAGES];
    #pragma unroll
    for (int s = 0; s < STAGES; s++) {
        Abuf[s] = sm + s * (A_FL + B_FL);
        Bbuf[s] = Abuf[s] + A_FL;
        a_u[s]  = smb + (uint32_t)(s * (A_FL + B_FL)) * 4u;
        b_u[s]  = a_u[s] + A_FL * 4u;
    }

    const int t    = threadIdx.x;
    const int lane = t & 31;
    const int wid  = t >> 5;
    const int wm   = wid & 3;
    const int wn   = wid >> 2;
    const int r    = lane >> 2;
    const int c    = lane & 3;

    const int is_k  = blockIdx.z & 1;
    const int khalf = blockIdx.z >> 1;

    const float* X    = is_k ? Xk : Xq;
    const float* W    = is_k ? Wk : Wq;
    float*       OutT = is_k ? g_k2t : g_q2t;

    const int m0 = blockIdx.x * BM;
    const int n0 = blockIdx.y * BN;
    const int k0 = khalf * KSPL;

    const float* Xb = X + (size_t)m0 * QD + k0;
    const float* Wb = W + (size_t)k0 * CD + n0;

    const int arow = t >> 4;             // 0..15 (+16 per it)
    const int aj   = t & 15;             // 16B chunk within 64-float row

    float acc[2][4][4] = {};

    // ---- prologue: tiles 0 and 1 ----
    #pragma unroll
    for (int p = 0; p < 2; p++) {
        const int kf = p * BK;
        #pragma unroll
        for (int it = 0; it < 8; it++) {         // A: 128 rows x 64 k
            const int row = arow + it * 16;
            cp_async16(a_u[p] + (uint32_t)(row * LDS_A + aj * 4) * 4,
                       Xb + (size_t)row * QD + kf + aj * 4);
        }
        #pragma unroll
        for (int it = 0; it < 4; it++) {         // B: 64 k-rows x 64 n
            const int krow = arow + it * 16;
            cp_async16(b_u[p] + (uint32_t)(krow * LDS_B + aj * 4) * 4,
                       Wb + (size_t)(kf + krow) * CD + aj * 4);
        }
        cp_commit();
    }

    for (int i = 0; i < NITER; i++) {
        if (i + 1 < NITER) cp_wait1(); else cp_wait0();
        __syncthreads();

        const int sb = i & 1;
        const float* As = Abuf[sb];
        const float* Bs = Bbuf[sb];

        #pragma unroll
        for (int kfi = 0; kfi < 8; kfi++) {
            const int kf = kfi * 8;
            uint32_t af[2][4], bf[4][2];
            #pragma unroll
            for (int mt = 0; mt < 2; mt++) {
                const int m = wm * 32 + mt * 16 + r;
                af[mt][0] = TF32_RN(__float_as_uint(As[(m    ) * LDS_A + kf + c    ]));
                af[mt][1] = TF32_RN(__float_as_uint(As[(m + 8) * LDS_A + kf + c    ]));
                af[mt][2] = TF32_RN(__float_as_uint(As[(m    ) * LDS_A + kf + c + 4]));
                af[mt][3] = TF32_RN(__float_as_uint(As[(m + 8) * LDS_A + kf + c + 4]));
            }
            #pragma unroll
            for (int nt = 0; nt < 4; nt++) {
                const int n = wn * 32 + nt * 8 + r;
                bf[nt][0] = TF32_RN(__float_as_uint(Bs[(kf + c    ) * LDS_B + n]));
                bf[nt][1] = TF32_RN(__float_as_uint(Bs[(kf + c + 4) * LDS_B + n]));
            }
            #pragma unroll
            for (int mt = 0; mt < 2; mt++)
                #pragma unroll
                for (int nt = 0; nt < 4; nt++)
                    mma_tf32(acc[mt][nt], af[mt], bf[nt]);
        }

        __syncthreads();                 // all warps done reading buf sb
        if (i + 2 < NITER) {
            const int kf = (i + 2) * BK;
            #pragma unroll
            for (int it = 0; it < 8; it++) {
                const int row = arow + it * 16;
                cp_async16(a_u[sb] + (uint32_t)(row * LDS_A + aj * 4) * 4,
                           Xb + (size_t)row * QD + kf + aj * 4);
            }
            #pragma unroll
            for (int it = 0; it < 4; it++) {
                const int krow = arow + it * 16;
                cp_async16(b_u[sb] + (uint32_t)(krow * LDS_B + aj * 4) * 4,
                           Wb + (size_t)(kf + krow) * CD + aj * 4);
            }
            cp_commit();
        }
    }

    // ---- epilogue: direct atomic accumulate into C-major scratch ----
    // acc[mt][nt] = { (m, n), (m, n+1), (m+8, n), (m+8, n+1) },
    // m = wm*32 + mt*16 + r, n = wn*32 + nt*8 + 2c.
    // OutT addr(m, n) = (b*CD + n0 + n)*TQ + m_ib + m.
    const int b_idx = m0 >> 9;
    const int m_ib  = m0 & 511;
    #pragma unroll
    for (int mt = 0; mt < 2; mt++) {
        const int m = wm * 32 + mt * 16 + r;
        #pragma unroll
        for (int nt = 0; nt < 4; nt++) {
            const int n = wn * 32 + nt * 8 + 2 * c;
            float* base = OutT + ((size_t)b_idx * CD + n0 + n) * TQ + m_ib + m;
            atomicAdd(base,          acc[mt][nt][0]);
            atomicAdd(base + TQ,     acc[mt][nt][1]);
            atomicAdd(base + 8,      acc[mt][nt][2]);
            atomicAdd(base + TQ + 8, acc[mt][nt][3]);
        }
    }
}

// ---------------------------------------------------------------------------
// Score kernel: MUFU-bound fp32 tanh core at the HW floor.
// out[b,q,k] = b + sum_c w[c]*tanh(q2[b,q,c]+k2[b,k,c])
// ---------------------------------------------------------------------------
__global__ __launch_bounds__(256) void score_kernel(
    const float* __restrict__ w_attn, const float* __restrict__ b_attn,
    float* __restrict__ out)
{
    const int b  = blockIdx.z;
    const int q0 = blockIdx.y * 32;
    const int k0 = blockIdx.x * 32;

    __shared__ float q_s[64][32];
    __shared__ float k_s[64][32];
    __shared__ float w_s[CD];

    const int t  = threadIdx.x;
    const int ty = t >> 5;
    const int tx = t & 31;

    w_s[t] = w_attn[t];

    const float* qbase = g_q2t + (size_t)b * CD * TQ + q0;
    const float* kbase = g_k2t + (size_t)b * CD * TK + k0;

    float acc0 = 0.f, acc1 = 0.f, acc2 = 0.f, acc3 = 0.f;

    for (int c0 = 0; c0 < CD; c0 += 64) {
        __syncthreads();
        #pragma unroll
        for (int rr = 0; rr < 2; rr++) {
            const int v    = t + rr * 256;
            const int row  = v >> 3;
            const int col4 = (v & 7) << 2;
            *(float4*)&q_s[row][col4] =
                *(const float4*)&qbase[(size_t)(c0 + row) * TQ + col4];
            *(float4*)&k_s[row][col4] =
                *(const float4*)&kbase[(size_t)(c0 + row) * TK + col4];
        }
        __syncthreads();

        #pragma unroll 8
        for (int cc = 0; cc < 64; cc++) {
            const float kv = k_s[cc][tx];
            const float w  = w_s[c0 + cc];
            acc0 += w * tanh_fast(q_s[cc][ty     ] + kv);
            acc1 += w * tanh_fast(q_s[cc][ty +  8] + kv);
            acc2 += w * tanh_fast(q_s[cc][ty + 16] + kv);
            acc3 += w * tanh_fast(q_s[cc][ty + 24] + kv);
        }
    }

    const float bias = b_attn[0];
    const size_t obase = ((size_t)b * TQ + q0) * TK + k0 + tx;
    out[obase + (size_t)(ty     ) * TK] = acc0 + bias;
    out[obase + (size_t)(ty +  8) * TK] = acc1 + bias;
    out[obase + (size_t)(ty + 16) * TK] = acc2 + bias;
    out[obase + (size_t)(ty + 24) * TK] = acc3 + bias;
}

extern "C" void kernel_launch(void* const* d_in, const int* in_sizes, int n_in,
                              void* d_out, int out_size)
{
    const float* query  = (const float*)d_in[0];
    const float* key    = (const float*)d_in[1];
    const float* Wq     = (const float*)d_in[2];
    const float* Wk     = (const float*)d_in[3];
    const float* w_attn = (const float*)d_in[4];
    const float* b_attn = (const float*)d_in[5];
    float* out = (float*)d_out;

    cudaFuncSetAttribute(proj_mma_kernel,
                         cudaFuncAttributeMaxDynamicSharedMemorySize, DYN_SMEM);

    // Zero the accumulation scratch (graph-capturable memset nodes).
    void* qp = nullptr; void* kp = nullptr;
    cudaGetSymbolAddress(&qp, g_q2t);
    cudaGetSymbolAddress(&kp, g_k2t);
    cudaMemsetAsync(qp, 0, sizeof(float) * B_ * CD * TQ);
    cudaMemsetAsync(kp, 0, sizeof(float) * B_ * CD * TK);

    dim3 pg((B_ * TQ) / BM, CD / BN, 4);       // (16, 4, 4) = 256 CTAs
    proj_mma_kernel<<<pg, 256, DYN_SMEM>>>(query, key, Wq, Wk);

    dim3 sg(TK / 32, TQ / 32, B_);             // (16, 16, 4)
    score_kernel<<<sg, 256>>>(w_attn, b_attn, out);
}

// round 12
// speedup vs baseline: 1.0256x; 1.0256x over previous
#include <cuda_runtime.h>
#include <cstdint>

#define B_  4
#define TQ  512
#define TK  512
#define QD  1024
#define CD  256

// Scratch: projected tensors TRANSPOSED [b][c][row] (C-major).
__device__ float g_q2t[B_ * CD * TQ];
__device__ float g_k2t[B_ * CD * TK];

__device__ __forceinline__ uint32_t smem_u32(const void* p) {
    uint32_t a;
    asm("{ .reg .u64 t; cvta.to.shared.u64 t, %1; cvt.u32.u64 %0, t; }"
        : "=r"(a) : "l"(p));
    return a;
}
__device__ __forceinline__ void cp_async16(uint32_t saddr, const void* g) {
    asm volatile("cp.async.cg.shared.global [%0], [%1], 16;" :: "r"(saddr), "l"(g));
}
__device__ __forceinline__ void cp_commit() {
    asm volatile("cp.async.commit_group;" ::: "memory");
}
__device__ __forceinline__ void cp_wait1() {
    asm volatile("cp.async.wait_group 1;" ::: "memory");
}
__device__ __forceinline__ void cp_wait0() {
    asm volatile("cp.async.wait_group 0;" ::: "memory");
}
__device__ __forceinline__ void mma_tf32(float* d, const uint32_t* a, const uint32_t* b) {
    asm volatile(
        "mma.sync.aligned.m16n8k8.row.col.f32.tf32.tf32.f32 "
        "{%0,%1,%2,%3}, {%4,%5,%6,%7}, {%8,%9}, {%0,%1,%2,%3};\n"
        : "+f"(d[0]), "+f"(d[1]), "+f"(d[2]), "+f"(d[3])
        : "r"(a[0]), "r"(a[1]), "r"(a[2]), "r"(a[3]), "r"(b[0]), "r"(b[1]));
}
__device__ __forceinline__ float tanh_fast(float x) {
    float y;
    asm("tanh.approx.f32 %0, %1;" : "=f"(y) : "f"(x));
    return y;
}
// Round fp32 bit pattern so tf32 truncation (drop 13 bits) becomes round-to-nearest.
#define TF32_RN(u) ((u) + 0x1000u)

// ---------------------------------------------------------------------------
// Projection via mma.sync tf32, small-tile / multi-CTA-per-SM variant.
// C[m][n] = sum_k X[m][k]*W[k][n]; output stored C-major transposed.
// BM=64, BN=64, BK=64; 4 warps (2M x 2N) of 32x32 warp tiles; 128 threads.
// 3-stage cp.async, 1 sync/iter. 256 CTAs -> 2 co-resident CTAs on most SMs;
// cross-CTA interleaving hides LDS latency + barrier drain.
// A smem [m][k] stride 68; B smem natural W layout [k][n] stride 72.
// ---------------------------------------------------------------------------
#define BM     64
#define BN     64
#define BK     64
#define LDS_A  68
#define LDS_B  72
#define A_FL   (BM * LDS_A)              // 4352 floats
#define B_FL   (BK * LDS_B)              // 4608 floats
#define NITER  (QD / BK)                 // 16
#define STG_LD 68
#define STAGES 3
#define NTHR   128
#define DYN_SMEM (STAGES * (A_FL + B_FL) * 4)   // 107520 B -> 2 CTAs/SM

__global__ __launch_bounds__(NTHR, 2) void proj_mma_kernel(
    const float* __restrict__ Xq, const float* __restrict__ Xk,
    const float* __restrict__ Wq, const float* __restrict__ Wk)
{
    extern __shared__ float sm[];
    const uint32_t smb = smem_u32(sm);

    float*   Abuf[STAGES];
    float*   Bbuf[STAGES];
    uint32_t a_u[STAGES], b_u[STAGES];
    #pragma unroll
    for (int s = 0; s < STAGES; s++) {
        Abuf[s] = sm + s * (A_FL + B_FL);
        Bbuf[s] = Abuf[s] + A_FL;
        a_u[s]  = smb + (uint32_t)(s * (A_FL + B_FL)) * 4u;
        b_u[s]  = a_u[s] + A_FL * 4u;
    }

    const int t    = threadIdx.x;
    const int lane = t & 31;
    const int wid  = t >> 5;             // 0..3
    const int wm   = wid & 1;            // 2 M-slices of 32
    const int wn   = wid >> 1;           // 2 N-slices of 32
    const int r    = lane >> 2;          // 0..7
    const int c    = lane & 3;           // 0..3

    const float* X    = blockIdx.z ? Xk : Xq;
    const float* W    = blockIdx.z ? Wk : Wq;
    float*       OutT = blockIdx.z ? g_k2t : g_q2t;

    const int m0 = blockIdx.x * BM;
    const int n0 = blockIdx.y * BN;

    const float* Xb = X + (size_t)m0 * QD;
    const float* Wb = W + n0;

    // cp.async mapping: 64-float rows = 16 chunks of 16B; 128 threads.
    const int arow = t >> 4;             // 0..7 (+8 per it)
    const int aj   = t & 15;             // chunk within row

    float acc[2][4][4] = {};

    // ---- prologue: tiles 0 and 1 ----
    #pragma unroll
    for (int p = 0; p < 2; p++) {
        const int kf = p * BK;
        #pragma unroll
        for (int it = 0; it < 8; it++) {         // A: 64 rows x 64 k
            const int row = arow + it * 8;
            cp_async16(a_u[p] + (uint32_t)(row * LDS_A + aj * 4) * 4,
                       Xb + (size_t)row * QD + kf + aj * 4);
        }
        #pragma unroll
        for (int it = 0; it < 8; it++) {         // B: 64 k-rows x 64 n
            const int krow = arow + it * 8;
            cp_async16(b_u[p] + (uint32_t)(krow * LDS_B + aj * 4) * 4,
                       Wb + (size_t)(kf + krow) * CD + aj * 4);
        }
        cp_commit();
    }

    for (int i = 0; i < NITER; i++) {
        if (i + 1 < NITER) cp_wait1(); else cp_wait0();
        __syncthreads();

        const int sb = i % STAGES;
        const float* As = Abuf[sb];
        const float* Bs = Bbuf[sb];

        #pragma unroll
        for (int kfi = 0; kfi < 8; kfi++) {
            const int kf = kfi * 8;
            uint32_t af[2][4], bf[4][2];
            #pragma unroll
            for (int mt = 0; mt < 2; mt++) {
                const int m = wm * 32 + mt * 16 + r;
                af[mt][0] = TF32_RN(__float_as_uint(As[(m    ) * LDS_A + kf + c    ]));
                af[mt][1] = TF32_RN(__float_as_uint(As[(m + 8) * LDS_A + kf + c    ]));
                af[mt][2] = TF32_RN(__float_as_uint(As[(m    ) * LDS_A + kf + c + 4]));
                af[mt][3] = TF32_RN(__float_as_uint(As[(m + 8) * LDS_A + kf + c + 4]));
            }
            #pragma unroll
            for (int nt = 0; nt < 4; nt++) {
                const int n = wn * 32 + nt * 8 + r;
                bf[nt][0] = TF32_RN(__float_as_uint(Bs[(kf + c    ) * LDS_B + n]));
                bf[nt][1] = TF32_RN(__float_as_uint(Bs[(kf + c + 4) * LDS_B + n]));
            }
            #pragma unroll
            for (int mt = 0; mt < 2; mt++)
                #pragma unroll
                for (int nt = 0; nt < 4; nt++)
                    mma_tf32(acc[mt][nt], af[mt], bf[nt]);
        }

        // prefetch tile i+2 into stage (i+2)%STAGES
        if (i + 2 < NITER) {
            const int nb = (i + 2) % STAGES;
            const int kf = (i + 2) * BK;
            #pragma unroll
            for (int it = 0; it < 8; it++) {
                const int row = arow + it * 8;
                cp_async16(a_u[nb] + (uint32_t)(row * LDS_A + aj * 4) * 4,
                           Xb + (size_t)row * QD + kf + aj * 4);
            }
            #pragma unroll
            for (int it = 0; it < 8; it++) {
                const int krow = arow + it * 8;
                cp_async16(b_u[nb] + (uint32_t)(krow * LDS_B + aj * 4) * 4,
                           Wb + (size_t)(kf + krow) * CD + aj * 4);
            }
        }
        cp_commit();
    }

    __syncthreads();

    // ---- epilogue: stage transposed [n][m], store C-major float4 ----
    float* stg = sm;                     // 64*68 = 4352 floats, fits
    #pragma unroll
    for (int mt = 0; mt < 2; mt++) {
        const int mlo = wm * 32 + mt * 16 + r;
        #pragma unroll
        for (int nt = 0; nt < 4; nt++) {
            const int n = wn * 32 + nt * 8 + 2 * c;
            stg[(n    ) * STG_LD + mlo    ] = acc[mt][nt][0];
            stg[(n + 1) * STG_LD + mlo    ] = acc[mt][nt][1];
            stg[(n    ) * STG_LD + mlo + 8] = acc[mt][nt][2];
            stg[(n + 1) * STG_LD + mlo + 8] = acc[mt][nt][3];
        }
    }
    __syncthreads();

    const int b_idx = m0 >> 9;           // 64 | 512, tiles never straddle
    const int m_ib  = m0 & 511;
    #pragma unroll
    for (int it = 0; it < 8; it++) {
        const int idx = t + it * NTHR;   // 0..1023 float4 chunks
        const int n   = idx >> 4;        // 0..63
        const int mj  = idx & 15;        // float4 index along m (0..15)
        float4 v = *(const float4*)&stg[n * STG_LD + mj * 4];
        *(float4*)&OutT[((size_t)b_idx * CD + n0 + n) * TQ + m_ib + mj * 4] = v;
    }
}

// ---------------------------------------------------------------------------
// Score kernel: MUFU-bound fp32 tanh core at the HW floor.
// out[b,q,k] = b + sum_c w[c]*tanh(q2[b,q,c]+k2[b,k,c])
// ---------------------------------------------------------------------------
__global__ __launch_bounds__(256) void score_kernel(
    const float* __restrict__ w_attn, const float* __restrict__ b_attn,
    float* __restrict__ out)
{
    const int b  = blockIdx.z;
    const int q0 = blockIdx.y * 32;
    const int k0 = blockIdx.x * 32;

    __shared__ float q_s[64][32];
    __shared__ float k_s[64][32];
    __shared__ float w_s[CD];

    const int t  = threadIdx.x;
    const int ty = t >> 5;
    const int tx = t & 31;

    w_s[t] = w_attn[t];

    const float* qbase = g_q2t + (size_t)b * CD * TQ + q0;
    const float* kbase = g_k2t + (size_t)b * CD * TK + k0;

    float acc0 = 0.f, acc1 = 0.f, acc2 = 0.f, acc3 = 0.f;

    for (int c0 = 0; c0 < CD; c0 += 64) {
        __syncthreads();
        #pragma unroll
        for (int rr = 0; rr < 2; rr++) {
            const int v    = t + rr * 256;
            const int row  = v >> 3;
            const int col4 = (v & 7) << 2;
            *(float4*)&q_s[row][col4] =
                *(const float4*)&qbase[(size_t)(c0 + row) * TQ + col4];
            *(float4*)&k_s[row][col4] =
                *(const float4*)&kbase[(size_t)(c0 + row) * TK + col4];
        }
        __syncthreads();

        #pragma unroll 8
        for (int cc = 0; cc < 64; cc++) {
            const float kv = k_s[cc][tx];
            const float w  = w_s[c0 + cc];
            acc0 += w * tanh_fast(q_s[cc][ty     ] + kv);
            acc1 += w * tanh_fast(q_s[cc][ty +  8] + kv);
            acc2 += w * tanh_fast(q_s[cc][ty + 16] + kv);
            acc3 += w * tanh_fast(q_s[cc][ty + 24] + kv);
        }
    }

    const float bias = b_attn[0];
    const size_t obase = ((size_t)b * TQ + q0) * TK + k0 + tx;
    out[obase + (size_t)(ty     ) * TK] = acc0 + bias;
    out[obase + (size_t)(ty +  8) * TK] = acc1 + bias;
    out[obase + (size_t)(ty + 16) * TK] = acc2 + bias;
    out[obase + (size_t)(ty + 24) * TK] = acc3 + bias;
}

extern "C" void kernel_launch(void* const* d_in, const int* in_sizes, int n_in,
                              void* d_out, int out_size)
{
    const float* query  = (const float*)d_in[0];
    const float* key    = (const float*)d_in[1];
    const float* Wq     = (const float*)d_in[2];
    const float* Wk     = (const float*)d_in[3];
    const float* w_attn = (const float*)d_in[4];
    const float* b_attn = (const float*)d_in[5];
    float* out = (float*)d_out;

    cudaFuncSetAttribute(proj_mma_kernel,
                         cudaFuncAttributeMaxDynamicSharedMemorySize, DYN_SMEM);

    dim3 pg((B_ * TQ) / BM, CD / BN, 2);       // (32, 4, 2) = 256 CTAs
    proj_mma_kernel<<<pg, NTHR, DYN_SMEM>>>(query, key, Wq, Wk);

    dim3 sg(TK / 32, TQ / 32, B_);             // (16, 16, 4)
    score_kernel<<<sg, 256>>>(w_attn, b_attn, out);
}

// round 13
// speedup vs baseline: 1.0777x; 1.0509x over previous
#include <cuda_runtime.h>
#include <cuda_fp16.h>
#include <cstdint>

#define B_  4
#define TQ  512
#define TK  512
#define QD  1024
#define CD  256

// Scratch: projected tensors TRANSPOSED [b][c][row] (C-major).
__device__ float  g_q2t[B_ * CD * TQ];
__device__ float  g_k2t[B_ * CD * TK];
// fp16 copies of inputs (conversion pre-pass).
__device__ __half g_xq_h[B_ * TQ * QD];    // query, same layout
__device__ __half g_xk_h[B_ * TK * QD];    // key
__device__ __half g_wqt_h[CD * QD];        // Wq^T [n][k]
__device__ __half g_wkt_h[CD * QD];        // Wk^T [n][k]

__device__ __forceinline__ uint32_t smem_u32(const void* p) {
    uint32_t a;
    asm("{ .reg .u64 t; cvta.to.shared.u64 t, %1; cvt.u32.u64 %0, t; }"
        : "=r"(a) : "l"(p));
    return a;
}
__device__ __forceinline__ void cp_async16(uint32_t saddr, const void* g) {
    asm volatile("cp.async.cg.shared.global [%0], [%1], 16;" :: "r"(saddr), "l"(g));
}
__device__ __forceinline__ void cp_commit() {
    asm volatile("cp.async.commit_group;" ::: "memory");
}
__device__ __forceinline__ void cp_wait1() {
    asm volatile("cp.async.wait_group 1;" ::: "memory");
}
__device__ __forceinline__ void cp_wait0() {
    asm volatile("cp.async.wait_group 0;" ::: "memory");
}
__device__ __forceinline__ void mma_f16(float* d, const uint32_t* a, const uint32_t* b) {
    asm volatile(
        "mma.sync.aligned.m16n8k16.row.col.f32.f16.f16.f32 "
        "{%0,%1,%2,%3}, {%4,%5,%6,%7}, {%8,%9}, {%0,%1,%2,%3};\n"
        : "+f"(d[0]), "+f"(d[1]), "+f"(d[2]), "+f"(d[3])
        : "r"(a[0]), "r"(a[1]), "r"(a[2]), "r"(a[3]), "r"(b[0]), "r"(b[1]));
}
__device__ __forceinline__ float tanh_fast(float x) {
    float y;
    asm("tanh.approx.f32 %0, %1;" : "=f"(y) : "f"(x));
    return y;
}
__device__ __forceinline__ uint32_t pack_h2(float lo, float hi) {
    __half2 h = __floats2half2_rn(lo, hi);
    return *(uint32_t*)&h;
}

// ---------------------------------------------------------------------------
// Convert pre-pass (one launch):
//   blocks [0, 2048): X -> half  (bid>>10 selects q/k; 2048 elems per block)
//   blocks [2048, 2560): W -> half transposed Wt[n][k] (32x32 tiles)
// ---------------------------------------------------------------------------
__global__ __launch_bounds__(256) void convert_kernel(
    const float* __restrict__ Xq, const float* __restrict__ Xk,
    const float* __restrict__ Wq, const float* __restrict__ Wk)
{
    const int bid = blockIdx.x;
    const int t   = threadIdx.x;

    if (bid < 2048) {
        const int    which = bid >> 10;            // 0 = q, 1 = k
        const size_t base  = (size_t)(bid & 1023) * 2048 + (size_t)t * 8;
        const float* src   = which ? Xk : Xq;
        __half*      dst   = which ? g_xk_h : g_xq_h;
        float4 v0 = *(const float4*)&src[base];
        float4 v1 = *(const float4*)&src[base + 4];
        uint4 o;
        o.x = pack_h2(v0.x, v0.y);
        o.y = pack_h2(v0.z, v0.w);
        o.z = pack_h2(v1.x, v1.y);
        o.w = pack_h2(v1.z, v1.w);
        *(uint4*)&dst[base] = o;
    } else {
        __shared__ float tile[32][33];
        const int bid2 = bid - 2048;               // 0..511
        const int z    = bid2 >> 8;                // 0 = Wq, 1 = Wk
        const int tidx = bid2 & 255;
        const int k0   = (tidx & 31) * 32;
        const int n0   = (tidx >> 5) * 32;
        const float* W  = z ? Wk : Wq;
        __half*      Wt = z ? g_wkt_h : g_wqt_h;
        const int tx = t & 31, ty = t >> 5;        // 32 x 8
        #pragma unroll
        for (int r = 0; r < 32; r += 8)
            tile[ty + r][tx] = W[(size_t)(k0 + ty + r) * CD + n0 + tx];
        __syncthreads();
        #pragma unroll
        for (int r = 0; r < 32; r += 8)
            Wt[(size_t)(n0 + ty + r) * QD + k0 + tx] = __float2half_rn(tile[tx][ty + r]);
    }
}

// ---------------------------------------------------------------------------
// Projection via mma.sync m16n8k16 fp16 (half the MMA instrs of tf32 k8).
// C[m][n] = sum_k X[m][k]*W[k][n]; fp32 accumulate; C-major transposed output.
// A smem [m][k] half, stride 72 halfs; B smem Wt [n][k] half, stride 72.
// Fragment LDS.32 loads k-pairs; banks (4r+c) mod 32 distinct for both.
// 8 warps = 4(M) x 2(N), warp tile 32x32, BK=64, 3-stage cp.async, 1 sync/iter.
// ---------------------------------------------------------------------------
#define BM     128
#define BN     64
#define BK     64
#define LDS_H  72                        // stride in halfs (144 B, 16B-aligned rows)
#define A_HL   (BM * LDS_H)              // 9216 halfs
#define B_HL   (BN * LDS_H)              // 4608 halfs
#define NITER  (QD / BK)                 // 16
#define STG_LD 132
#define STAGES 3
#define DYN_SMEM (STAGES * (A_HL + B_HL) * 2)   // 82944 B

__global__ __launch_bounds__(256) void proj_mma_kernel()
{
    extern __shared__ __half smh[];
    const uint32_t smb = smem_u32(smh);

    __half*  Abuf[STAGES];
    __half*  Bbuf[STAGES];
    uint32_t a_u[STAGES], b_u[STAGES];
    #pragma unroll
    for (int s = 0; s < STAGES; s++) {
        Abuf[s] = smh + s * (A_HL + B_HL);
        Bbuf[s] = Abuf[s] + A_HL;
        a_u[s]  = smb + (uint32_t)(s * (A_HL + B_HL)) * 2u;
        b_u[s]  = a_u[s] + A_HL * 2u;
    }

    const int t    = threadIdx.x;
    const int lane = t & 31;
    const int wid  = t >> 5;
    const int wm   = wid & 3;
    const int wn   = wid >> 2;
    const int r    = lane >> 2;
    const int c    = lane & 3;

    const __half* X    = blockIdx.z ? g_xk_h : g_xq_h;
    const __half* Wt   = blockIdx.z ? g_wkt_h : g_wqt_h;
    float*        OutT = blockIdx.z ? g_k2t : g_q2t;

    const int m0 = blockIdx.x * BM;
    const int n0 = blockIdx.y * BN;

    const __half* Xb = X  + (size_t)m0 * QD;
    const __half* Wb = Wt + (size_t)n0 * QD;

    // cp.async: 64-half rows = 128 B = 8 chunks of 16B (8 halfs).
    const int arow = t >> 3;             // 0..31 (+32 per it)
    const int aj   = t & 7;              // chunk within row

    float acc[2][4][4] = {};

    // ---- prologue: tiles 0 and 1 ----
    #pragma unroll
    for (int p = 0; p < 2; p++) {
        const int kf = p * BK;
        #pragma unroll
        for (int it = 0; it < 4; it++) {         // A: 128 rows
            const int row = arow + it * 32;
            cp_async16(a_u[p] + (uint32_t)(row * LDS_H + aj * 8) * 2,
                       Xb + (size_t)row * QD + kf + aj * 8);
        }
        #pragma unroll
        for (int it = 0; it < 2; it++) {         // B: 64 n-rows
            const int row = arow + it * 32;
            cp_async16(b_u[p] + (uint32_t)(row * LDS_H + aj * 8) * 2,
                       Wb + (size_t)row * QD + kf + aj * 8);
        }
        cp_commit();
    }

    for (int i = 0; i < NITER; i++) {
        if (i + 1 < NITER) cp_wait1(); else cp_wait0();
        __syncthreads();

        const int sb = i % STAGES;
        const __half* As = Abuf[sb];
        const __half* Bs = Bbuf[sb];

        #pragma unroll
        for (int kk = 0; kk < 4; kk++) {         // 4 x k16 per BK=64
            const int kf = kk * 16;
            uint32_t af[2][4], bf[4][2];
            #pragma unroll
            for (int mt = 0; mt < 2; mt++) {
                const int m = wm * 32 + mt * 16 + r;
                af[mt][0] = *(const uint32_t*)&As[(m    ) * LDS_H + kf     + 2 * c];
                af[mt][1] = *(const uint32_t*)&As[(m + 8) * LDS_H + kf     + 2 * c];
                af[mt][2] = *(const uint32_t*)&As[(m    ) * LDS_H + kf + 8 + 2 * c];
                af[mt][3] = *(const uint32_t*)&As[(m + 8) * LDS_H + kf + 8 + 2 * c];
            }
            #pragma unroll
            for (int nt = 0; nt < 4; nt++) {
                const int n = wn * 32 + nt * 8 + r;
                bf[nt][0] = *(const uint32_t*)&Bs[n * LDS_H + kf     + 2 * c];
                bf[nt][1] = *(const uint32_t*)&Bs[n * LDS_H + kf + 8 + 2 * c];
            }
            #pragma unroll
            for (int mt = 0; mt < 2; mt++)
                #pragma unroll
                for (int nt = 0; nt < 4; nt++)
                    mma_f16(acc[mt][nt], af[mt], bf[nt]);
        }

        // prefetch tile i+2 into stage (i+2)%STAGES
        if (i + 2 < NITER) {
            const int nb = (i + 2) % STAGES;
            const int kf = (i + 2) * BK;
            #pragma unroll
            for (int it = 0; it < 4; it++) {
                const int row = arow + it * 32;
                cp_async16(a_u[nb] + (uint32_t)(row * LDS_H + aj * 8) * 2,
                           Xb + (size_t)row * QD + kf + aj * 8);
            }
            #pragma unroll
            for (int it = 0; it < 2; it++) {
                const int row = arow + it * 32;
                cp_async16(b_u[nb] + (uint32_t)(row * LDS_H + aj * 8) * 2,
                           Wb + (size_t)row * QD + kf + aj * 8);
            }
        }
        cp_commit();
    }

    __syncthreads();

    // ---- epilogue: stage transposed [n][m] (f32), store C-major float4 ----
    float* stg = (float*)smh;            // 64*132 floats = 33792 B, fits
    #pragma unroll
    for (int mt = 0; mt < 2; mt++) {
        const int mlo = wm * 32 + mt * 16 + r;
        #pragma unroll
        for (int nt = 0; nt < 4; nt++) {
            const int n = wn * 32 + nt * 8 + 2 * c;
            stg[(n    ) * STG_LD + mlo    ] = acc[mt][nt][0];
            stg[(n + 1) * STG_LD + mlo    ] = acc[mt][nt][1];
            stg[(n    ) * STG_LD + mlo + 8] = acc[mt][nt][2];
            stg[(n + 1) * STG_LD + mlo + 8] = acc[mt][nt][3];
        }
    }
    __syncthreads();

    const int b_idx = m0 >> 9;
    const int m_ib  = m0 & 511;
    #pragma unroll
    for (int it = 0; it < 8; it++) {
        const int idx = t + it * 256;
        const int n   = idx >> 5;
        const int mj  = idx & 31;
        float4 v = *(const float4*)&stg[n * STG_LD + mj * 4];
        *(float4*)&OutT[((size_t)b_idx * CD + n0 + n) * TQ + m_ib + mj * 4] = v;
    }
}

// ---------------------------------------------------------------------------
// Score kernel: MUFU-bound fp32 tanh core at the HW floor.
// out[b,q,k] = b + sum_c w[c]*tanh(q2[b,q,c]+k2[b,k,c])
// ---------------------------------------------------------------------------
__global__ __launch_bounds__(256) void score_kernel(
    const float* __restrict__ w_attn, const float* __restrict__ b_attn,
    float* __restrict__ out)
{
    const int b  = blockIdx.z;
    const int q0 = blockIdx.y * 32;
    const int k0 = blockIdx.x * 32;

    __shared__ float q_s[64][32];
    __shared__ float k_s[64][32];
    __shared__ float w_s[CD];

    const int t  = threadIdx.x;
    const int ty = t >> 5;
    const int tx = t & 31;

    w_s[t] = w_attn[t];

    const float* qbase = g_q2t + (size_t)b * CD * TQ + q0;
    const float* kbase = g_k2t + (size_t)b * CD * TK + k0;

    float acc0 = 0.f, acc1 = 0.f, acc2 = 0.f, acc3 = 0.f;

    for (int c0 = 0; c0 < CD; c0 += 64) {
        __syncthreads();
        #pragma unroll
        for (int rr = 0; rr < 2; rr++) {
            const int v    = t + rr * 256;
            const int row  = v >> 3;
            const int col4 = (v & 7) << 2;
            *(float4*)&q_s[row][col4] =
                *(const float4*)&qbase[(size_t)(c0 + row) * TQ + col4];
            *(float4*)&k_s[row][col4] =
                *(const float4*)&kbase[(size_t)(c0 + row) * TK + col4];
        }
        __syncthreads();

        #pragma unroll 8
        for (int cc = 0; cc < 64; cc++) {
            const float kv = k_s[cc][tx];
            const float w  = w_s[c0 + cc];
            acc0 += w * tanh_fast(q_s[cc][ty     ] + kv);
            acc1 += w * tanh_fast(q_s[cc][ty +  8] + kv);
            acc2 += w * tanh_fast(q_s[cc][ty + 16] + kv);
            acc3 += w * tanh_fast(q_s[cc][ty + 24] + kv);
        }
    }

    const float bias = b_attn[0];
    const size_t obase = ((size_t)b * TQ + q0) * TK + k0 + tx;
    out[obase + (size_t)(ty     ) * TK] = acc0 + bias;
    out[obase + (size_t)(ty +  8) * TK] = acc1 + bias;
    out[obase + (size_t)(ty + 16) * TK] = acc2 + bias;
    out[obase + (size_t)(ty + 24) * TK] = acc3 + bias;
}

extern "C" void kernel_launch(void* const* d_in, const int* in_sizes, int n_in,
                              void* d_out, int out_size)
{
    const float* query  = (const float*)d_in[0];
    const float* key    = (const float*)d_in[1];
    const float* Wq     = (const float*)d_in[2];
    const float* Wk     = (const float*)d_in[3];
    const float* w_attn = (const float*)d_in[4];
    const float* b_attn = (const float*)d_in[5];
    float* out = (float*)d_out;

    cudaFuncSetAttribute(proj_mma_kernel,
                         cudaFuncAttributeMaxDynamicSharedMemorySize, DYN_SMEM);

    convert_kernel<<<2560, 256>>>(query, key, Wq, Wk);

    dim3 pg((B_ * TQ) / BM, CD / BN, 2);       // (16, 4, 2) = 128 CTAs
    proj_mma_kernel<<<pg, 256, DYN_SMEM>>>();

    dim3 sg(TK / 32, TQ / 32, B_);             // (16, 16, 4)
    score_kernel<<<sg, 256>>>(w_attn, b_attn, out);
}